// round 7
// baseline (speedup 1.0000x reference)
#include <cuda_runtime.h>
#include <cstdint>

#define S_MAX   2146592
#define TPB     256
#define EPS_F   1e-8f

// ---------------- device globals (static scratch; no runtime allocation) ----------------
__device__ unsigned g_resbits[S_MAX];
__device__ unsigned g_hists[4][256];
__device__ double   g_base[4];            // sp, sg, spp, spg over all valid
__device__ double   g_rsum[4];            // refit sums
__device__ int      g_n, g_rn;
__device__ volatile unsigned g_count;     // barrier arrivals
__device__ volatile unsigned g_gen;       // barrier generation

// ---------------- software grid barrier (all blocks co-resident by construction) ----------------
__device__ __forceinline__ void grid_sync(int nb) {
    __syncthreads();
    if (threadIdx.x == 0) {
        __threadfence();
        unsigned gen = g_gen;
        unsigned arrived = atomicAdd((unsigned*)&g_count, 1u);
        if (arrived == (unsigned)nb - 1u) {
            g_count = 0u;
            __threadfence();
            g_gen = gen + 1u;
        } else {
            while (g_gen == gen) { }
        }
        __threadfence();
    }
    __syncthreads();
}

// ---------------- mask accessor (format decided at runtime) ----------------
__device__ __forceinline__ bool mask_at(const void* m, int j, int mode) {
    if (mode == 0) return ((const unsigned char*)m)[j] != 0;
    if (mode == 1) return ((const int*)m)[j] != 0;
    return ((const float*)m)[j] != 0.0f;
}

__device__ __forceinline__ void affine_fit(double n, double sp, double sg,
                                           double spp, double spg,
                                           double& s, double& b) {
    double det = spp * n - sp * sp;
    if (fabs(det) >= 1e-8) {
        s = (spg * n - sp * sg) / det;
        b = (spp * sg - sp * spg) / det;
    } else {
        s = spg / fmax(spp, 1e-8);
        b = 0.0;
    }
}

// ---------------- one persistent kernel: the whole pipeline ----------------
__global__ void __launch_bounds__(TPB) k_fused(
    const float* __restrict__ pred, const float* __restrict__ gt,
    const void* __restrict__ mask, float* __restrict__ out,
    int S, int out_size, int NB)
{
    __shared__ unsigned s_hist[256];
    __shared__ unsigned s_cls[4];
    __shared__ unsigned s_bin;
    __shared__ int      s_krem;

    const int t = threadIdx.x;
    const int bid = blockIdx.x;
    const int gid = bid * TPB + t;
    const int stride = NB * TPB;
    const int lane = t & 31;

    // ---- phase 0: block 0 zeroes shared accumulators; all blocks redundantly detect mask fmt
    if (bid == 0) {
        for (int i = t; i < 4 * 256; i += TPB) ((unsigned*)g_hists)[i] = 0u;
        if (t < 4) { g_base[t] = 0.0; g_rsum[t] = 0.0; }
        if (t == 0) { g_n = 0; g_rn = 0; }
    }
    {
        const unsigned char* m8 = (const unsigned char*)mask;
        int nd = S < 65536 ? S : 65536;
        unsigned cnt = 0;
        for (int j = t; j < nd; j += TPB) cnt += (m8[j] != 0);
        if (t < 4) s_cls[t] = 0u;
        __syncthreads();
        // stride-4-preserving reduce: lane L (<4) accumulates class L
        cnt += __shfl_down_sync(0xffffffffu, cnt, 16);
        cnt += __shfl_down_sync(0xffffffffu, cnt, 8);
        cnt += __shfl_down_sync(0xffffffffu, cnt, 4);
        if (lane < 4 && cnt) atomicAdd(&s_cls[lane], cnt);
        __syncthreads();
    }
    int mode;
    {
        unsigned c0 = s_cls[0], c1 = s_cls[1], c2 = s_cls[2], c3 = s_cls[3];
        if (c0 && c1)      mode = 0;   // u8 mask: all byte offsets populated
        else if (c2 || c3) mode = 2;   // f32 1.0f -> nonzero bytes at offsets 2,3
        else               mode = 1;   // i32 0/1  -> nonzero bytes at offset 0 only
    }
    grid_sync(NB);   // B1: accumulators zeroed

    // ---- phase 1: base sums over all valid
    {
        float sp = 0.f, sg = 0.f, spp = 0.f, spg = 0.f; int n = 0;
        for (int j = gid; j < S; j += stride) {
            float p = pred[j], g = gt[j];
            if (mask_at(mask, j, mode) && g > EPS_F && p > EPS_F) {
                n++; sp += p; sg += g;
                spp = fmaf(p, p, spp); spg = fmaf(p, g, spg);
            }
        }
#pragma unroll
        for (int o = 16; o; o >>= 1) {
            sp  += __shfl_down_sync(0xffffffffu, sp,  o);
            sg  += __shfl_down_sync(0xffffffffu, sg,  o);
            spp += __shfl_down_sync(0xffffffffu, spp, o);
            spg += __shfl_down_sync(0xffffffffu, spg, o);
        }
        n = __reduce_add_sync(0xffffffffu, n);
        if (lane == 0) {
            atomicAdd(&g_base[0], (double)sp);  atomicAdd(&g_base[1], (double)sg);
            atomicAdd(&g_base[2], (double)spp); atomicAdd(&g_base[3], (double)spg);
            atomicAdd(&g_n, n);
        }
    }
    grid_sync(NB);   // B2: base sums complete

    // ---- base fit, computed redundantly by every thread (identical results)
    const int n_valid = g_n;
    float s0, b0;
    {
        double sd, bd;
        affine_fit((double)n_valid, g_base[0], g_base[1], g_base[2], g_base[3], sd, bd);
        s0 = (float)sd; b0 = (float)bd;
    }
    int kremain = (n_valid - 1) / 2;   // lower median index
    unsigned prefix = 0u;

    // ---- phases 2-5: exact median via 4x radix-256 select on residual bits
#pragma unroll 1
    for (int pass = 0; pass < 4; pass++) {
        int shift = 24 - 8 * pass;
        s_hist[t] = 0u;
        __syncthreads();
        if (pass == 0) {
            for (int j = gid; j < S; j += stride) {
                float p = pred[j], g = gt[j];
                bool v = mask_at(mask, j, mode) && (g > EPS_F) && (p > EPS_F);
                float r = fabsf(g - fmaf(s0, p, b0));
                unsigned bits = v ? __float_as_uint(r) : 0xFFFFFFFFu;
                g_resbits[j] = bits;
                atomicAdd(&s_hist[bits >> 24], 1u);
            }
        } else {
            unsigned himask = 0xFFFFFFFFu << (shift + 8);
            for (int j = gid; j < S; j += stride) {
                unsigned b = g_resbits[j];
                if (((b ^ prefix) & himask) == 0u)
                    atomicAdd(&s_hist[(b >> shift) & 255u], 1u);
            }
        }
        __syncthreads();
        if (s_hist[t]) atomicAdd(&g_hists[pass][t], s_hist[t]);
        grid_sync(NB);           // histogram complete
        // per-block redundant scan (identical integer results everywhere)
        s_hist[t] = g_hists[pass][t];
        __syncthreads();
        if (t == 0) {
            long long rem = kremain;
            unsigned long long cum = 0;
            int bin = 255;
            for (int i = 0; i < 256; i++) {
                unsigned c = s_hist[i];
                if ((long long)(cum + c) > rem) { bin = i; break; }
                cum += c;
            }
            s_bin = (unsigned)bin;
            s_krem = (int)(rem - (long long)cum);
        }
        __syncthreads();
        prefix |= s_bin << shift;
        kremain = s_krem;
        __syncthreads();
    }
    const float th = __uint_as_float(prefix) * 1.5f;
    const unsigned th_bits = __float_as_uint(th);

    // ---- phase 6: refit on inliers of the base model (resbits encodes validity + |r|)
    {
        float sp = 0.f, sg = 0.f, spp = 0.f, spg = 0.f; int n = 0;
        for (int j = gid; j < S; j += stride) {
            if (g_resbits[j] < th_bits) {     // nonneg-float bits are order-preserving
                float p = pred[j], g = gt[j];
                n++; sp += p; sg += g;
                spp = fmaf(p, p, spp); spg = fmaf(p, g, spg);
            }
        }
#pragma unroll
        for (int o = 16; o; o >>= 1) {
            sp  += __shfl_down_sync(0xffffffffu, sp,  o);
            sg  += __shfl_down_sync(0xffffffffu, sg,  o);
            spp += __shfl_down_sync(0xffffffffu, spp, o);
            spg += __shfl_down_sync(0xffffffffu, spg, o);
        }
        n = __reduce_add_sync(0xffffffffu, n);
        if (lane == 0) {
            atomicAdd(&g_rsum[0], (double)sp);  atomicAdd(&g_rsum[1], (double)sg);
            atomicAdd(&g_rsum[2], (double)spp); atomicAdd(&g_rsum[3], (double)spg);
            atomicAdd(&g_rn, n);
        }
    }
    grid_sync(NB);   // B7: refit sums complete

    // ---- final fit (redundant per thread) + output
    float scale, shiftv;
    {
        double sd, bd;
        affine_fit((double)g_rn, g_rsum[0], g_rsum[1], g_rsum[2], g_rsum[3], sd, bd);
        bool use = g_rn > 10;
        scale  = use ? (float)sd : s0;
        shiftv = use ? (float)bd : b0;
        scale = fminf(fmaxf(scale, 0.01f), 100.f);
    }
    for (int j = gid; j < S; j += stride)
        out[j] = fmaxf(fmaf(scale, pred[j], shiftv), 0.f);
    if (gid == 0) {
        if (S < out_size)     out[S] = scale;
        if (S + 1 < out_size) out[S + 1] = shiftv;
    }
}

// ---------------- launch ----------------
extern "C" void kernel_launch(void* const* d_in, const int* in_sizes, int n_in,
                              void* d_out, int out_size) {
    const float* pred = (const float*)d_in[0];
    const float* gt   = (const float*)d_in[1];
    const void*  mask = d_in[2];
    float* out = (float*)d_out;
    int S = in_sizes[0];

    // all-co-resident grid: occupancy-derived, deadlock-safe for the software barrier
    int dev = 0, nsm = 0, bpm = 0;
    cudaGetDevice(&dev);
    cudaDeviceGetAttribute(&nsm, cudaDevAttrMultiProcessorCount, dev);
    cudaOccupancyMaxActiveBlocksPerMultiprocessor(&bpm, k_fused, TPB, 0);
    if (nsm <= 0) nsm = 148;
    if (bpm <= 0) bpm = 1;
    int NB = nsm * bpm;

    k_fused<<<NB, TPB>>>(pred, gt, mask, out, S, out_size, NB);
}